// round 13
// baseline (speedup 1.0000x reference)
#include <cuda_runtime.h>
#include <cuda_fp16.h>
#include <math.h>

#define B 64
#define T 256
#define D 512
#define G4 2048
#define M_ROWS (B * T)   // 16384
#define DIN2 1024

typedef unsigned long long ull;

// ---------------- release/acquire barrier primitives ----------------
__device__ __forceinline__ void red_release_add(unsigned* p, unsigned v) {
    asm volatile("red.release.gpu.global.add.u32 [%0], %1;"
                 :: "l"(p), "r"(v) : "memory");
}
__device__ __forceinline__ unsigned ld_acquire(const unsigned* p) {
    unsigned v;
    asm volatile("ld.acquire.gpu.global.u32 %0, [%1];"
                 : "=r"(v) : "l"(p) : "memory");
    return v;
}
__device__ __forceinline__ unsigned prmtb(unsigned a, unsigned b, unsigned sel) {
    unsigned r;
    asm("prmt.b32 %0, %1, %2, %3;" : "=r"(r) : "r"(a), "r"(b), "r"(sel));
    return r;
}

// ---------------- warp-MMA primitives (standard PTX; HMMA on sm_103) ----------
__device__ __forceinline__ void ldsm_x4(unsigned* r, unsigned addr) {
    asm volatile("ldmatrix.sync.aligned.m8n8.x4.shared.b16 {%0,%1,%2,%3}, [%4];"
        : "=r"(r[0]), "=r"(r[1]), "=r"(r[2]), "=r"(r[3]) : "r"(addr));
}
__device__ __forceinline__ void ldsm_x2(unsigned* r, unsigned addr) {
    asm volatile("ldmatrix.sync.aligned.m8n8.x2.shared.b16 {%0,%1}, [%2];"
        : "=r"(r[0]), "=r"(r[1]) : "r"(addr));
}
__device__ __forceinline__ void mma16816(float* c, const unsigned* a, const unsigned* b) {
    asm volatile(
        "mma.sync.aligned.m16n8k16.row.col.f32.f16.f16.f32 "
        "{%0,%1,%2,%3}, {%4,%5,%6,%7}, {%8,%9}, {%0,%1,%2,%3};"
        : "+f"(c[0]), "+f"(c[1]), "+f"(c[2]), "+f"(c[3])
        : "r"(a[0]), "r"(a[1]), "r"(a[2]), "r"(a[3]), "r"(b[0]), "r"(b[1]));
}

// ---------------- device scratch ----------------
__device__ float g_xz_f[(size_t)M_ROWS * G4];
__device__ float g_xz_b[(size_t)M_ROWS * G4];
__device__ float g_y1[(size_t)M_ROWS * DIN2];
__device__ unsigned g_hpk[2][2][B * D];     // packed (f16 hi | f16 lo<<16)
__device__ float g_hfin[2 * B * D];
__device__ float g_c[2 * B * D];
__device__ unsigned char g_mask[M_ROWS];
__device__ unsigned g_cta_arr[2][64][32];   // [dir][cta][pad]
__device__ unsigned g_cnt[2][32];           // [dir][pad]
// pre-transposed weights: [slot][n * K + k] f16 hi/lo (slot = layer*2 + dir)
__device__ __half g_wt_hi[4][(size_t)G4 * 1024];
__device__ __half g_wt_lo[4][(size_t)G4 * 1024];

// ---------------- one-time weight transform: W[K][2048] f32 -> [n][K] f16 hi/lo
__global__ void wtrans_kernel(const float* __restrict__ W, int K, int slot) {
    __shared__ float ts[32][68];
    int tid = threadIdx.x;
    int n0 = blockIdx.x << 6, k0 = blockIdx.y << 5;
    __half* whi = &g_wt_hi[slot][0];
    __half* wlo = &g_wt_lo[slot][0];
#pragma unroll
    for (int j = 0; j < 2; j++) {
        int idx = tid + (j << 8);
        int kr = idx >> 4, nq = idx & 15;
        *(float4*)&ts[kr][nq << 2] =
            *(const float4*)&W[(size_t)(k0 + kr) * G4 + n0 + (nq << 2)];
    }
    __syncthreads();
#pragma unroll
    for (int j = 0; j < 2; j++) {
        int idx = tid + (j << 8);
        int n = idx >> 3, kq = idx & 7;
        float v[4];
        __half h[4], lo[4];
#pragma unroll
        for (int c = 0; c < 4; c++) {
            v[c] = ts[(kq << 2) + c][n];
            h[c] = __float2half_rn(v[c]);
            lo[c] = __float2half_rn(v[c] - __half2float(h[c]));
        }
        size_t off = (size_t)(n0 + n) * K + k0 + (kq << 2);
        *(__half2*)&whi[off]     = __halves2half2(h[0], h[1]);
        *(__half2*)&whi[off + 2] = __halves2half2(h[2], h[3]);
        *(__half2*)&wlo[off]     = __halves2half2(lo[0], lo[1]);
        *(__half2*)&wlo[off + 2] = __halves2half2(lo[2], lo[3]);
    }
}

// ---------------- fused: mask + zero packed h + barrier reset ----------------
__global__ void maskinit_kernel(const float* __restrict__ X) {
    int tid = threadIdx.x;
    int gidx = blockIdx.x * 128 + tid;
    if (gidx < 2 * 2 * B * D) ((unsigned*)g_hpk)[gidx] = 0u;
    if (gidx < 2 * 64 * 32) ((unsigned*)g_cta_arr)[gidx] = 0u;
    if (gidx < 2 * 32) ((unsigned*)g_cnt)[gidx] = 0u;
    int row = blockIdx.x * 4 + (tid >> 5);
    int lane = tid & 31;
    const float* p = X + (size_t)row * D;
    int any = 0;
    for (int k = lane; k < D; k += 32) any |= (p[k] != 0.0f);
    any = __any_sync(0xffffffffu, any);
    if (lane == 0) g_mask[row] = (unsigned char)any;
}

// ---------------- HMMA GEMM: C[M,2048] = A[M,K] @ W[K,2048] + bias ----------
// split-f16 3-term (AhiWhi + AhiWlo + AloWhi), fp32 accum.
// BM=BN=128, BK=32, 512 threads (16 warps, m64 x n16 each), double-buffered.
// smem row stride 80B (40 f16) => ldmatrix conflict-free (80 % 128 coprime walk).
#define GTILE 10240                 // 128 rows * 80 B
#define GBUF  (4 * GTILE)           // AHI, ALO, WHI, WLO
#define SMEM_GEMM (2 * GBUF)        // 81920 B

__global__ void __launch_bounds__(512) gemm_bias_hmma(
    const float* __restrict__ Aext, int a_is_y1, int wslot,
    const float* __restrict__ bias, int c_sel, int K)
{
    extern __shared__ char gsm[];
    unsigned sbase;
    asm("{ .reg .u64 t; cvta.to.shared.u64 t, %1; cvt.u32.u64 %0, t; }"
        : "=r"(sbase) : "l"(gsm));

    const float* A = a_is_y1 ? g_y1 : Aext;
    float* C = c_sel ? g_xz_b : g_xz_f;
    const __half* wthi = &g_wt_hi[wslot][0];
    const __half* wtlo = &g_wt_lo[wslot][0];

    int tid = threadIdx.x, l = tid & 31, w = tid >> 5;
    int m0 = blockIdx.y << 7, n0 = blockIdx.x << 7;
    int mh = w & 1, nO = w >> 1;                 // warp: m-half, n-16-block

    float acc[4][2][4];
#pragma unroll
    for (int mt = 0; mt < 4; mt++)
#pragma unroll
        for (int nt = 0; nt < 2; nt++)
#pragma unroll
            for (int i = 0; i < 4; i++) acc[mt][nt][i] = 0.f;

    // staging indices
    int am[2], akq[2];
#pragma unroll
    for (int j = 0; j < 2; j++) {
        int idx = tid + (j << 9);
        am[j] = idx >> 3; akq[j] = idx & 7;
    }
    int wn = tid >> 2, wkc = tid & 3;

    float4 aR[2];
    uint4 whR, wlR;

#define G_LDG(k0)                                                              \
    {                                                                          \
        aR[0] = *(const float4*)&A[(size_t)(m0 + am[0]) * K + (k0) + (akq[0] << 2)]; \
        aR[1] = *(const float4*)&A[(size_t)(m0 + am[1]) * K + (k0) + (akq[1] << 2)]; \
        whR = *(const uint4*)&wthi[(size_t)(n0 + wn) * K + (k0) + (wkc << 3)]; \
        wlR = *(const uint4*)&wtlo[(size_t)(n0 + wn) * K + (k0) + (wkc << 3)]; \
    }

#define G_STS(buf)                                                             \
    {                                                                          \
        char* bb = gsm + (buf) * GBUF;                                         \
        _Pragma("unroll")                                                      \
        for (int j = 0; j < 2; j++) {                                          \
            const float* av = (const float*)&aR[j];                           \
            __half h0 = __float2half_rn(av[0]), h1 = __float2half_rn(av[1]);  \
            __half h2 = __float2half_rn(av[2]), h3 = __float2half_rn(av[3]);  \
            __half l0 = __float2half_rn(av[0] - __half2float(h0));            \
            __half l1 = __float2half_rn(av[1] - __half2float(h1));            \
            __half l2 = __float2half_rn(av[2] - __half2float(h2));            \
            __half l3 = __float2half_rn(av[3] - __half2float(h3));            \
            int o = am[j] * 80 + (akq[j] << 3);                               \
            *(__half2*)(bb + o)     = __halves2half2(h0, h1);                 \
            *(__half2*)(bb + o + 4) = __halves2half2(h2, h3);                 \
            *(__half2*)(bb + GTILE + o)     = __halves2half2(l0, l1);         \
            *(__half2*)(bb + GTILE + o + 4) = __halves2half2(l2, l3);         \
        }                                                                      \
        *(uint4*)(bb + 2 * GTILE + wn * 80 + (wkc << 4)) = whR;               \
        *(uint4*)(bb + 3 * GTILE + wn * 80 + (wkc << 4)) = wlR;               \
    }

    G_LDG(0);
    G_STS(0);
    __syncthreads();

    int KT = K >> 5;
    for (int kt = 0; kt < KT; kt++) {
        int cur = kt & 1;
        if (kt + 1 < KT) { G_LDG((kt + 1) << 5); }

        unsigned abase = sbase + cur * GBUF;
#pragma unroll
        for (int kk = 0; kk < 2; kk++) {
            unsigned ahf[4][4], alf[4][4];
#pragma unroll
            for (int mt = 0; mt < 4; mt++) {
                int row = (mh << 6) + (mt << 4) + (l & 15);
                unsigned addr = abase + row * 80 + (kk << 5) + ((l >> 4) << 4);
                ldsm_x4(ahf[mt], addr);
                ldsm_x4(alf[mt], addr + GTILE);
            }
#pragma unroll
            for (int nt = 0; nt < 2; nt++) {
                int n = (nO << 4) + (nt << 3) + (l & 7);
                unsigned baddr = abase + 2 * GTILE + n * 80 + (kk << 5)
                                 + ((l >> 3) & 1) * 16;
                unsigned bh[2], bl[2];
                ldsm_x2(bh, baddr);
                ldsm_x2(bl, baddr + GTILE);
#pragma unroll
                for (int mt = 0; mt < 4; mt++) {
                    mma16816(acc[mt][nt], ahf[mt], bh);
                    mma16816(acc[mt][nt], ahf[mt], bl);
                    mma16816(acc[mt][nt], alf[mt], bh);
                }
            }
        }
        if (kt + 1 < KT) {
            __syncthreads();
            G_STS(cur ^ 1);
            __syncthreads();
        }
    }

    // epilogue: bias + f32 store
#pragma unroll
    for (int mt = 0; mt < 4; mt++) {
#pragma unroll
        for (int nt = 0; nt < 2; nt++) {
            int row = m0 + (mh << 6) + (mt << 4) + (l >> 2);
            int col = n0 + (nO << 4) + (nt << 3) + ((l & 3) << 1);
            float2 bz = *(const float2*)&bias[col];
            float2 v0 = {acc[mt][nt][0] + bz.x, acc[mt][nt][1] + bz.y};
            float2 v1 = {acc[mt][nt][2] + bz.x, acc[mt][nt][3] + bz.y};
            *(float2*)&C[(size_t)row * G4 + col] = v0;
            *(float2*)&C[(size_t)(row + 8) * G4 + col] = v1;
        }
    }
#undef G_LDG
#undef G_STS
}

// ---------------- persistent scan: warp-MMA split-fp16 recurrence ----------------
// (unchanged from R12 — verified)
#define HSTRIDE_B 1040
#define OFF_HHI  0
#define OFF_HLO  (64 * HSTRIDE_B)
#define OFF_UHI  (2 * 64 * HSTRIDE_B)
#define OFF_ULO  (OFF_UHI + 32 * HSTRIDE_B)
#define OFF_MASK (OFF_ULO + 32 * HSTRIDE_B)
#define SMEM_SCAN (OFF_MASK + 16384)

__global__ void __launch_bounds__(512) lstm_scan_kernel(
    const float* __restrict__ Uf, const float* __restrict__ Ub,
    float* dout, int out_is_y1)
{
    extern __shared__ char smb[];
    unsigned smem_base;
    asm("{ .reg .u64 t; cvta.to.shared.u64 t, %1; cvt.u32.u64 %0, t; }"
        : "=r"(smem_base) : "l"(smb));
    unsigned char* mask_s = (unsigned char*)(smb + OFF_MASK);
    float* zp = (float*)(smb + OFF_HHI);

    int tid = threadIdx.x;
    int lane = tid & 31, wid = tid >> 5;
    int dir = blockIdx.x >> 6;
    int cta = blockIdx.x & 63;
    int u0 = cta << 3;

    const float* U = dir ? Ub : Uf;
    const float* xz = dir ? g_xz_b : g_xz_f;
    float* outb = (out_is_y1 ? g_y1 : dout) + dir * D;
    unsigned* my_arr = &g_cta_arr[dir][cta][0];
    unsigned* my_cnt = &g_cnt[dir][0];

    // ---- stage U slice ONCE as hi/lo f16, [n=32][k=512] row-major ----
    for (int i = tid; i < 32 * 512; i += 512) {
        int n = i & 31, k = i >> 5;
        int col = ((n >> 3) << 9) + u0 + (n & 7);
        float v = U[(size_t)k * G4 + col];
        __half hv = __float2half_rn(v);
        __half lv = __float2half_rn(v - __half2float(hv));
        *(__half*)(smb + OFF_UHI + n * HSTRIDE_B + (k << 1)) = hv;
        *(__half*)(smb + OFF_ULO + n * HSTRIDE_B + (k << 1)) = lv;
    }
    {
        const int4* msrc = (const int4*)g_mask;
        int4* mdst = (int4*)mask_s;
        for (int i = tid; i < M_ROWS / 16; i += 512) mdst[i] = msrc[i];
    }
    __syncthreads();

    int b = tid >> 3, u = tid & 7;
    int cb = u0 + u;
    int mg = wid & 3, ks = wid >> 2;
    int arow = (mg << 4) + (lane & 15);
    unsigned a_hi = smem_base + OFF_HHI + arow * HSTRIDE_B + ((lane >> 4) << 4);
    unsigned a_lo = a_hi + (OFF_HLO - OFF_HHI);
    unsigned b_base = smem_base + OFF_UHI + ((lane & 7)) * HSTRIDE_B
                      + (((lane >> 3) & 1) << 4);

    float c_reg = 0.f, h_reg = 0.f, po_reg = 0.f;

    for (int s = 0; s < T; s++) {
        int ping = s & 1;
        int t_d = dir ? (T - 1 - s) : s;
        const unsigned* hsrc = &g_hpk[ping][dir][0];
        unsigned* hdst = &g_hpk[ping ^ 1][dir][0];

        int row = b * T + t_d;
        size_t xr = (size_t)row * G4;
        float xz0 = __ldcg(&xz[xr + cb]);
        float xz1 = __ldcg(&xz[xr + 512 + cb]);
        float xz2 = __ldcg(&xz[xr + 1024 + cb]);
        float xz3 = __ldcg(&xz[xr + 1536 + cb]);
        unsigned mrv = mask_s[row];

#pragma unroll
        for (int it = 0; it < 16; it++) {
            int idx = tid + (it << 9);
            int hb = idx >> 7, k0 = (idx & 127) << 2;
            uint4 wv = __ldcg((const uint4*)&hsrc[(hb << 9) + k0]);
            unsigned hiA = prmtb(wv.x, wv.y, 0x5410), hiB = prmtb(wv.z, wv.w, 0x5410);
            unsigned loA = prmtb(wv.x, wv.y, 0x7632), loB = prmtb(wv.z, wv.w, 0x7632);
            unsigned o = hb * HSTRIDE_B + (k0 << 1);
            *(uint2*)(smb + OFF_HHI + o) = make_uint2(hiA, hiB);
            *(uint2*)(smb + OFF_HLO + o) = make_uint2(loA, loB);
        }
        __syncthreads();

        float acc[16];
#pragma unroll
        for (int i = 0; i < 16; i++) acc[i] = 0.f;

#pragma unroll
        for (int kc = 0; kc < 8; kc++) {
            unsigned kbyte = (unsigned)(((ks << 7) + (kc << 4)) << 1);
            unsigned ahi[4], alo[4];
            ldsm_x4(ahi, a_hi + kbyte);
            ldsm_x4(alo, a_lo + kbyte);
#pragma unroll
            for (int nt = 0; nt < 4; nt++) {
                unsigned baddr = b_base + (unsigned)(nt << 3) * HSTRIDE_B + kbyte;
                unsigned bhi[2], blo[2];
                ldsm_x2(bhi, baddr);
                ldsm_x2(blo, baddr + (OFF_ULO - OFF_UHI));
                mma16816(acc + (nt << 2), ahi, bhi);
                mma16816(acc + (nt << 2), ahi, blo);
                mma16816(acc + (nt << 2), alo, bhi);
            }
        }
        __syncthreads();

        {
            float* myzp = zp + ks * (64 * 36);
            int g = lane >> 2, tt = lane & 3;
#pragma unroll
            for (int nt = 0; nt < 4; nt++) {
                int r0 = (mg << 4) + g, ccol = (nt << 3) + (tt << 1);
                myzp[r0 * 36 + ccol]           = acc[(nt << 2) + 0];
                myzp[r0 * 36 + ccol + 1]       = acc[(nt << 2) + 1];
                myzp[(r0 + 8) * 36 + ccol]     = acc[(nt << 2) + 2];
                myzp[(r0 + 8) * 36 + ccol + 1] = acc[(nt << 2) + 3];
            }
        }
        __syncthreads();

        {
            float zi = xz0, zf = xz1, zg = xz2, zo = xz3;
#pragma unroll
            for (int p = 0; p < 4; p++) {
                const float* zb = zp + p * (64 * 36) + b * 36;
                zi += zb[u];
                zf += zb[8 + u];
                zg += zb[16 + u];
                zo += zb[24 + u];
            }
            float iv = 1.0f / (1.0f + expf(-zi));
            float fv = 1.0f / (1.0f + expf(-zf));
            float gv = tanhf(zg);
            float ov = 1.0f / (1.0f + expf(-zo));
            float c_new = fv * c_reg + iv * gv;
            float h_new = ov * tanhf(c_new);
            bool m = mrv != 0u;
            c_reg  = m ? c_new : c_reg;
            h_reg  = m ? h_new : h_reg;
            po_reg = m ? h_new : po_reg;
            __half hh = __float2half_rn(h_reg);
            __half hl = __float2half_rn(h_reg - __half2float(hh));
            unsigned pk = (unsigned)__half_as_ushort(hh) |
                          ((unsigned)__half_as_ushort(hl) << 16);
            hdst[(b << 9) + cb] = pk;
        }

        bool not_last = (s + 1 < T);
        if (not_last) {
            red_release_add(my_arr, 1u);
        }

        outb[(size_t)row * 1024 + cb] = po_reg;

        if (not_last) {
            if (tid == 0) {
                unsigned tgt_cta = 512u * (unsigned)(s + 1);
                while (ld_acquire(my_arr) < tgt_cta) __nanosleep(64);
                red_release_add(my_cnt, 1u);
                unsigned tgt_all = 64u * (unsigned)(s + 1);
                while (ld_acquire(my_cnt) < tgt_all) __nanosleep(64);
            }
            __syncthreads();
        }
    }

    g_hfin[dir * (B * D) + b * D + cb] = h_reg;
    g_c[dir * (B * D) + b * D + cb] = c_reg;
}

// ---------------- final hidden/cell concat ----------------
__global__ void finalize_kernel(float* dout, int out_size) {
    int i = blockIdx.x * blockDim.x + threadIdx.x;
    if (i >= B * 2 * D) return;
    size_t hoff = (size_t)B * T * 1024;
    if ((size_t)out_size < hoff + 2 * (size_t)(B * 2 * D)) return;
    int b = i >> 10, j = i & 1023;
    int dir = j >> 9, u = j & 511;
    int sidx = dir * (B * D) + b * D + u;
    dout[hoff + i] = g_hfin[sidx];
    dout[hoff + B * 2 * D + i] = g_c[sidx];
}

// ---------------- host orchestration ----------------
extern "C" void kernel_launch(void* const* d_in, const int* in_sizes, int n_in,
                              void* d_out, int out_size) {
    const float* X   = (const float*)d_in[0];
    const float* Wf1 = (const float*)d_in[1];
    const float* Uf1 = (const float*)d_in[2];
    const float* bf1 = (const float*)d_in[3];
    const float* Wb1 = (const float*)d_in[4];
    const float* Ub1 = (const float*)d_in[5];
    const float* bb1 = (const float*)d_in[6];
    const float* Wf2 = (const float*)d_in[7];
    const float* Uf2 = (const float*)d_in[8];
    const float* bf2 = (const float*)d_in[9];
    const float* Wb2 = (const float*)d_in[10];
    const float* Ub2 = (const float*)d_in[11];
    const float* bb2 = (const float*)d_in[12];
    float* out = (float*)d_out;

    cudaFuncSetAttribute(lstm_scan_kernel,
                         cudaFuncAttributeMaxDynamicSharedMemorySize, SMEM_SCAN);
    cudaFuncSetAttribute(gemm_bias_hmma,
                         cudaFuncAttributeMaxDynamicSharedMemorySize, SMEM_GEMM);

    dim3 ggrid(G4 / 128, M_ROWS / 128);
    dim3 wg1(G4 / 64, 512 / 32), wg2(G4 / 64, 1024 / 32);

    // weight transforms (one-time, inside graph)
    wtrans_kernel<<<wg1, 256>>>(Wf1, 512, 0);
    wtrans_kernel<<<wg1, 256>>>(Wb1, 512, 1);
    wtrans_kernel<<<wg2, 256>>>(Wf2, 1024, 2);
    wtrans_kernel<<<wg2, 256>>>(Wb2, 1024, 3);

    maskinit_kernel<<<M_ROWS / 4, 128>>>(X);

    // ---- layer 1 ----
    gemm_bias_hmma<<<ggrid, 512, SMEM_GEMM>>>(X, 0, 0, bf1, 0, 512);
    gemm_bias_hmma<<<ggrid, 512, SMEM_GEMM>>>(X, 0, 1, bb1, 1, 512);
    lstm_scan_kernel<<<128, 512, SMEM_SCAN>>>(Uf1, Ub1, out, 1);

    // ---- layer 2 ----
    gemm_bias_hmma<<<ggrid, 512, SMEM_GEMM>>>(nullptr, 1, 2, bf2, 0, 1024);
    gemm_bias_hmma<<<ggrid, 512, SMEM_GEMM>>>(nullptr, 1, 3, bb2, 1, 1024);
    maskinit_kernel<<<M_ROWS / 4, 128>>>(X);
    lstm_scan_kernel<<<128, 512, SMEM_SCAN>>>(Uf2, Ub2, out, 0);

    finalize_kernel<<<256, 256>>>(out, out_size);
}

// round 14
// speedup vs baseline: 1.2667x; 1.2667x over previous
#include <cuda_runtime.h>
#include <cuda_fp16.h>
#include <math.h>

#define B 64
#define T 256
#define D 512
#define G4 2048
#define M_ROWS (B * T)   // 16384
#define DIN2 1024

typedef unsigned long long ull;

// ---------------- f32x2 helpers (input GEMM kernel) ----------------
__device__ __forceinline__ void fma2(ull &d, ull a, ull b) {
    asm("fma.rn.f32x2 %0, %1, %2, %0;" : "+l"(d) : "l"(a), "l"(b));
}
__device__ __forceinline__ ull dup2(float v) {
    ull r; unsigned u = __float_as_uint(v);
    asm("mov.b64 %0, {%1, %1};" : "=l"(r) : "r"(u));
    return r;
}
__device__ __forceinline__ float2 unpk(ull v) {
    float2 f;
    asm("mov.b64 {%0, %1}, %2;" : "=f"(f.x), "=f"(f.y) : "l"(v));
    return f;
}

// ---------------- release/acquire barrier primitives ----------------
__device__ __forceinline__ void red_release_add(unsigned* p, unsigned v) {
    asm volatile("red.release.gpu.global.add.u32 [%0], %1;"
                 :: "l"(p), "r"(v) : "memory");
}
__device__ __forceinline__ unsigned ld_acquire(const unsigned* p) {
    unsigned v;
    asm volatile("ld.acquire.gpu.global.u32 %0, [%1];"
                 : "=r"(v) : "l"(p) : "memory");
    return v;
}

// ---------------- warp-MMA primitives (standard PTX; HMMA on sm_103) ----------
__device__ __forceinline__ void ldsm_x4(unsigned* r, unsigned addr) {
    asm volatile("ldmatrix.sync.aligned.m8n8.x4.shared.b16 {%0,%1,%2,%3}, [%4];"
        : "=r"(r[0]), "=r"(r[1]), "=r"(r[2]), "=r"(r[3]) : "r"(addr));
}
__device__ __forceinline__ void ldsm_x2(unsigned* r, unsigned addr) {
    asm volatile("ldmatrix.sync.aligned.m8n8.x2.shared.b16 {%0,%1}, [%2];"
        : "=r"(r[0]), "=r"(r[1]) : "r"(addr));
}
__device__ __forceinline__ void mma16816(float* c, const unsigned* a, const unsigned* b) {
    asm volatile(
        "mma.sync.aligned.m16n8k16.row.col.f32.f16.f16.f32 "
        "{%0,%1,%2,%3}, {%4,%5,%6,%7}, {%8,%9}, {%0,%1,%2,%3};"
        : "+f"(c[0]), "+f"(c[1]), "+f"(c[2]), "+f"(c[3])
        : "r"(a[0]), "r"(a[1]), "r"(a[2]), "r"(a[3]), "r"(b[0]), "r"(b[1]));
}

// ---------------- device scratch ----------------
__device__ float g_xz_f[(size_t)M_ROWS * G4];
__device__ float g_xz_b[(size_t)M_ROWS * G4];
__device__ float g_y1[(size_t)M_ROWS * DIN2];
// pre-split h halves: [which(hi=0,lo=1)][ping][dir][B*D] f16
__device__ __half g_hs[2][2][2][B * D];
__device__ float g_hfin[2 * B * D];
__device__ float g_c[2 * B * D];
__device__ unsigned char g_mask[M_ROWS];
__device__ unsigned g_cta_arr[2][64][32];   // [dir][cta][pad]
__device__ unsigned g_cnt[2][32];           // [dir][pad]

// ---------------- fused: mask + zero split h + barrier reset ----------------
__global__ void maskinit_kernel(const float* __restrict__ X) {
    int tid = threadIdx.x;
    int gidx = blockIdx.x * 128 + tid;
    if (gidx < 2 * 2 * 2 * B * D / 2) ((unsigned*)g_hs)[gidx] = 0u;
    if (gidx < 2 * 64 * 32) ((unsigned*)g_cta_arr)[gidx] = 0u;
    if (gidx < 2 * 32) ((unsigned*)g_cnt)[gidx] = 0u;
    int row = blockIdx.x * 4 + (tid >> 5);
    int lane = tid & 31;
    const float* p = X + (size_t)row * D;
    int any = 0;
    for (int k = lane; k < D; k += 32) any |= (p[k] != 0.0f);
    any = __any_sync(0xffffffffu, any);
    if (lane == 0) g_mask[row] = (unsigned char)any;
}

// ---------------- FFMA2 GEMM: C[M,2048] = A[M,K] @ W[K,2048] + bias ----------
__global__ void __launch_bounds__(256, 2) gemm_bias_kernel(
    const float* __restrict__ Aext, int a_is_y1,
    const float* __restrict__ W, const float* __restrict__ bias,
    int c_sel, int K)
{
    const float* A = a_is_y1 ? g_y1 : Aext;
    float* C = c_sel ? g_xz_b : g_xz_f;

    __shared__ float As[2][16 * 128];
    __shared__ float Bs[2][16 * 128];

    int tid = threadIdx.x;
    int m0 = blockIdx.y << 7, n0 = blockIdx.x << 7;
    int warp = tid >> 5, lane = tid & 31;
    int wm = (warp & 3) << 5, wn = (warp >> 2) << 6;
    int lm = (lane >> 3) << 2, ln = (lane & 7) << 2;
    int am = tid & 127, akg = tid >> 7;
    int bn4 = tid & 31, bk0 = tid >> 5;

    ull acc[8][4];
#pragma unroll
    for (int r = 0; r < 8; r++)
#pragma unroll
        for (int s = 0; s < 4; s++) acc[r][s] = 0ULL;

    float4 aR[2], bR[2];
    const size_t arow = (size_t)(m0 + am) * K;

#define LDG_TILE(k0)                                                          \
    aR[0] = *(const float4*)&A[arow + (k0) + (akg << 2)];                     \
    aR[1] = *(const float4*)&A[arow + (k0) + ((akg + 2) << 2)];               \
    bR[0] = *(const float4*)&W[(size_t)((k0) + bk0) * G4 + n0 + (bn4 << 2)];  \
    bR[1] = *(const float4*)&W[(size_t)((k0) + bk0 + 8) * G4 + n0 + (bn4 << 2)];

#define STS_TILE(buf)                                                         \
    {                                                                         \
        float* Ad = As[buf]; float* Bd = Bs[buf];                             \
        Ad[((akg << 2) + 0) * 128 + am] = aR[0].x;                            \
        Ad[((akg << 2) + 1) * 128 + am] = aR[0].y;                            \
        Ad[((akg << 2) + 2) * 128 + am] = aR[0].z;                            \
        Ad[((akg << 2) + 3) * 128 + am] = aR[0].w;                            \
        Ad[(((akg + 2) << 2) + 0) * 128 + am] = aR[1].x;                      \
        Ad[(((akg + 2) << 2) + 1) * 128 + am] = aR[1].y;                      \
        Ad[(((akg + 2) << 2) + 2) * 128 + am] = aR[1].z;                      \
        Ad[(((akg + 2) << 2) + 3) * 128 + am] = aR[1].w;                      \
        *(float4*)&Bd[bk0 * 128 + (bn4 << 2)] = bR[0];                        \
        *(float4*)&Bd[(bk0 + 8) * 128 + (bn4 << 2)] = bR[1];                  \
    }

    LDG_TILE(0);
    STS_TILE(0);
    __syncthreads();

    int KT = K >> 4;
    for (int kt = 0; kt < KT; kt++) {
        int cur = kt & 1;
        if (kt + 1 < KT) { LDG_TILE((kt + 1) << 4); }
        const float* Ab = As[cur];
        const float* Bb = Bs[cur];
#pragma unroll
        for (int kk = 0; kk < 16; kk++) {
            float4 a0 = *(const float4*)&Ab[kk * 128 + wm + lm];
            float4 a1 = *(const float4*)&Ab[kk * 128 + wm + lm + 16];
            ulonglong2 b0 = *(const ulonglong2*)&Bb[kk * 128 + wn + ln];
            ulonglong2 b1 = *(const ulonglong2*)&Bb[kk * 128 + wn + ln + 32];
            ull ap[8];
            ap[0] = dup2(a0.x); ap[1] = dup2(a0.y); ap[2] = dup2(a0.z); ap[3] = dup2(a0.w);
            ap[4] = dup2(a1.x); ap[5] = dup2(a1.y); ap[6] = dup2(a1.z); ap[7] = dup2(a1.w);
#pragma unroll
            for (int r = 0; r < 8; r++) {
                fma2(acc[r][0], ap[r], b0.x);
                fma2(acc[r][1], ap[r], b0.y);
                fma2(acc[r][2], ap[r], b1.x);
                fma2(acc[r][3], ap[r], b1.y);
            }
        }
        if (kt + 1 < KT) {
            STS_TILE(cur ^ 1);
            __syncthreads();
        }
    }

    float4 bias0 = *(const float4*)&bias[n0 + wn + ln];
    float4 bias1 = *(const float4*)&bias[n0 + wn + ln + 32];
#pragma unroll
    for (int r = 0; r < 8; r++) {
        int mrow = m0 + wm + lm + (r < 4 ? r : 12 + r);
        float2 p0 = unpk(acc[r][0]), p1 = unpk(acc[r][1]);
        float2 p2 = unpk(acc[r][2]), p3 = unpk(acc[r][3]);
        float4 v0 = {p0.x + bias0.x, p0.y + bias0.y, p1.x + bias0.z, p1.y + bias0.w};
        float4 v1 = {p2.x + bias1.x, p2.y + bias1.y, p3.x + bias1.z, p3.y + bias1.w};
        size_t crow = (size_t)mrow * G4 + n0 + wn + ln;
        *(float4*)&C[crow] = v0;
        *(float4*)&C[crow + 32] = v1;
    }
#undef LDG_TILE
#undef STS_TILE
}

// ---------------- persistent scan: warp-MMA split-fp16 recurrence ----------------
// R12-verified structure; staging is now a pure copy (h pre-split in gmem).
#define HSTRIDE_B 1040
#define OFF_HHI  0
#define OFF_HLO  (64 * HSTRIDE_B)
#define OFF_UHI  (2 * 64 * HSTRIDE_B)
#define OFF_ULO  (OFF_UHI + 32 * HSTRIDE_B)
#define OFF_MASK (OFF_ULO + 32 * HSTRIDE_B)
#define SMEM_SCAN (OFF_MASK + 16384)

__global__ void __launch_bounds__(512) lstm_scan_kernel(
    const float* __restrict__ Uf, const float* __restrict__ Ub,
    float* dout, int out_is_y1)
{
    extern __shared__ char smb[];
    unsigned smem_base;
    asm("{ .reg .u64 t; cvta.to.shared.u64 t, %1; cvt.u32.u64 %0, t; }"
        : "=r"(smem_base) : "l"(smb));
    unsigned char* mask_s = (unsigned char*)(smb + OFF_MASK);
    float* zp = (float*)(smb + OFF_HHI);

    int tid = threadIdx.x;
    int lane = tid & 31, wid = tid >> 5;
    int dir = blockIdx.x >> 6;
    int cta = blockIdx.x & 63;
    int u0 = cta << 3;

    const float* U = dir ? Ub : Uf;
    const float* xz = dir ? g_xz_b : g_xz_f;
    float* outb = (out_is_y1 ? g_y1 : dout) + dir * D;
    unsigned* my_arr = &g_cta_arr[dir][cta][0];
    unsigned* my_cnt = &g_cnt[dir][0];

    // ---- stage U slice ONCE as hi/lo f16, [n=32][k=512] row-major ----
    for (int i = tid; i < 32 * 512; i += 512) {
        int n = i & 31, k = i >> 5;
        int col = ((n >> 3) << 9) + u0 + (n & 7);
        float v = U[(size_t)k * G4 + col];
        __half hv = __float2half_rn(v);
        __half lv = __float2half_rn(v - __half2float(hv));
        *(__half*)(smb + OFF_UHI + n * HSTRIDE_B + (k << 1)) = hv;
        *(__half*)(smb + OFF_ULO + n * HSTRIDE_B + (k << 1)) = lv;
    }
    {
        const int4* msrc = (const int4*)g_mask;
        int4* mdst = (int4*)mask_s;
        for (int i = tid; i < M_ROWS / 16; i += 512) mdst[i] = msrc[i];
    }
    __syncthreads();

    int b = tid >> 3, u = tid & 7;
    int cb = u0 + u;
    int mg = wid & 3, ks = wid >> 2;
    int arow = (mg << 4) + (lane & 15);
    unsigned a_hi = smem_base + OFF_HHI + arow * HSTRIDE_B + ((lane >> 4) << 4);
    unsigned a_lo = a_hi + (OFF_HLO - OFF_HHI);
    unsigned b_base = smem_base + OFF_UHI + ((lane & 7)) * HSTRIDE_B
                      + (((lane >> 3) & 1) << 4);

    float c_reg = 0.f, h_reg = 0.f, po_reg = 0.f;

    for (int s = 0; s < T; s++) {
        int ping = s & 1;
        int t_d = dir ? (T - 1 - s) : s;
        const __half* hs_hi = &g_hs[0][ping][dir][0];
        const __half* hs_lo = &g_hs[1][ping][dir][0];
        __half* hd_hi = &g_hs[0][ping ^ 1][dir][0];
        __half* hd_lo = &g_hs[1][ping ^ 1][dir][0];

        // ---- prefetch xz (long latency, issued first) + mask ----
        int row = b * T + t_d;
        size_t xr = (size_t)row * G4;
        float xz0 = __ldcg(&xz[xr + cb]);
        float xz1 = __ldcg(&xz[xr + 512 + cb]);
        float xz2 = __ldcg(&xz[xr + 1024 + cb]);
        float xz3 = __ldcg(&xz[xr + 1536 + cb]);
        unsigned mrv = mask_s[row];

        // ---- stage h: pure uint4 copy of pre-split hi/lo tiles ----
#pragma unroll
        for (int it = 0; it < 8; it++) {
            int idx = tid + (it << 9);        // 0..4095
            int hb = idx >> 6, ck = idx & 63;
            uint4 vh = __ldcg((const uint4*)(hs_hi + (hb << 9)) + ck);
            uint4 vl = __ldcg((const uint4*)(hs_lo + (hb << 9)) + ck);
            unsigned o = hb * HSTRIDE_B + (ck << 4);
            *(uint4*)(smb + OFF_HHI + o) = vh;
            *(uint4*)(smb + OFF_HLO + o) = vl;
        }
        __syncthreads();

        // ---- z partial = h(mg) @ U over k-slab ks, via HMMA ----
        float acc[16];
#pragma unroll
        for (int i = 0; i < 16; i++) acc[i] = 0.f;

#pragma unroll
        for (int kc = 0; kc < 8; kc++) {
            unsigned kbyte = (unsigned)(((ks << 7) + (kc << 4)) << 1);
            unsigned ahi[4], alo[4];
            ldsm_x4(ahi, a_hi + kbyte);
            ldsm_x4(alo, a_lo + kbyte);
#pragma unroll
            for (int nt = 0; nt < 4; nt++) {
                unsigned baddr = b_base + (unsigned)(nt << 3) * HSTRIDE_B + kbyte;
                unsigned bhi[2], blo[2];
                ldsm_x2(bhi, baddr);
                ldsm_x2(blo, baddr + (OFF_ULO - OFF_UHI));
                mma16816(acc + (nt << 2), ahi, bhi);
                mma16816(acc + (nt << 2), ahi, blo);
                mma16816(acc + (nt << 2), alo, bhi);
            }
        }
        __syncthreads();   // all h-tile reads done; zp aliasing now safe

        // ---- write k-slab partials (4 disjoint buffers) ----
        {
            float* myzp = zp + ks * (64 * 36);
            int g = lane >> 2, tt = lane & 3;
#pragma unroll
            for (int nt = 0; nt < 4; nt++) {
                int r0 = (mg << 4) + g, ccol = (nt << 3) + (tt << 1);
                myzp[r0 * 36 + ccol]           = acc[(nt << 2) + 0];
                myzp[r0 * 36 + ccol + 1]       = acc[(nt << 2) + 1];
                myzp[(r0 + 8) * 36 + ccol]     = acc[(nt << 2) + 2];
                myzp[(r0 + 8) * 36 + ccol + 1] = acc[(nt << 2) + 3];
            }
        }
        __syncthreads();

        // ---- gates + state update (1 element per thread) ----
        {
            float zi = xz0, zf = xz1, zg = xz2, zo = xz3;
#pragma unroll
            for (int p = 0; p < 4; p++) {
                const float* zb = zp + p * (64 * 36) + b * 36;
                zi += zb[u];
                zf += zb[8 + u];
                zg += zb[16 + u];
                zo += zb[24 + u];
            }
            float iv = 1.0f / (1.0f + expf(-zi));
            float fv = 1.0f / (1.0f + expf(-zf));
            float gv = tanhf(zg);
            float ov = 1.0f / (1.0f + expf(-zo));
            float c_new = fv * c_reg + iv * gv;
            float h_new = ov * tanhf(c_new);
            bool m = mrv != 0u;
            c_reg  = m ? c_new : c_reg;
            h_reg  = m ? h_new : h_reg;
            po_reg = m ? h_new : po_reg;
            __half hh = __float2half_rn(h_reg);
            __half hl = __float2half_rn(h_reg - __half2float(hh));
            hd_hi[(b << 9) + cb] = hh;
            hd_lo[(b << 9) + cb] = hl;
        }

        bool not_last = (s + 1 < T);
        if (not_last) {
            // every thread: release-arrive (orders own h stores first)
            red_release_add(my_arr, 1u);
        }

        // ---- per-timestep output write (overlaps barrier) ----
        outb[(size_t)row * 1024 + cb] = po_reg;

        if (not_last) {
            if (tid == 0) {
                unsigned tgt_cta = 512u * (unsigned)(s + 1);
                while (ld_acquire(my_arr) < tgt_cta) __nanosleep(64);
                red_release_add(my_cnt, 1u);
                unsigned tgt_all = 64u * (unsigned)(s + 1);
                while (ld_acquire(my_cnt) < tgt_all) __nanosleep(64);
            }
            __syncthreads();
        }
    }

    g_hfin[dir * (B * D) + b * D + cb] = h_reg;
    g_c[dir * (B * D) + b * D + cb] = c_reg;
}

// ---------------- final hidden/cell concat ----------------
__global__ void finalize_kernel(float* dout, int out_size) {
    int i = blockIdx.x * blockDim.x + threadIdx.x;
    if (i >= B * 2 * D) return;
    size_t hoff = (size_t)B * T * 1024;
    if ((size_t)out_size < hoff + 2 * (size_t)(B * 2 * D)) return;
    int b = i >> 10, j = i & 1023;
    int dir = j >> 9, u = j & 511;
    int sidx = dir * (B * D) + b * D + u;
    dout[hoff + i] = g_hfin[sidx];
    dout[hoff + B * 2 * D + i] = g_c[sidx];
}

// ---------------- host orchestration ----------------
extern "C" void kernel_launch(void* const* d_in, const int* in_sizes, int n_in,
                              void* d_out, int out_size) {
    const float* X   = (const float*)d_in[0];
    const float* Wf1 = (const float*)d_in[1];
    const float* Uf1 = (const float*)d_in[2];
    const float* bf1 = (const float*)d_in[3];
    const float* Wb1 = (const float*)d_in[4];
    const float* Ub1 = (const float*)d_in[5];
    const float* bb1 = (const float*)d_in[6];
    const float* Wf2 = (const float*)d_in[7];
    const float* Uf2 = (const float*)d_in[8];
    const float* bf2 = (const float*)d_in[9];
    const float* Wb2 = (const float*)d_in[10];
    const float* Ub2 = (const float*)d_in[11];
    const float* bb2 = (const float*)d_in[12];
    float* out = (float*)d_out;

    cudaFuncSetAttribute(lstm_scan_kernel,
                         cudaFuncAttributeMaxDynamicSharedMemorySize, SMEM_SCAN);

    dim3 ggrid(G4 / 128, M_ROWS / 128);

    // launch order puts scans at positions 4 and 8 (ncu capture slots)
    maskinit_kernel<<<M_ROWS / 4, 128>>>(X);                       // 1
    gemm_bias_kernel<<<ggrid, 256>>>(X, 0, Wf1, bf1, 0, 512);      // 2
    gemm_bias_kernel<<<ggrid, 256>>>(X, 0, Wb1, bb1, 1, 512);      // 3
    lstm_scan_kernel<<<128, 512, SMEM_SCAN>>>(Uf1, Ub1, out, 1);   // 4

    gemm_bias_kernel<<<ggrid, 256>>>(nullptr, 1, Wf2, bf2, 0, 1024); // 5
    gemm_bias_kernel<<<ggrid, 256>>>(nullptr, 1, Wb2, bb2, 1, 1024); // 6
    maskinit_kernel<<<M_ROWS / 4, 128>>>(X);                         // 7
    lstm_scan_kernel<<<128, 512, SMEM_SCAN>>>(Uf2, Ub2, out, 0);     // 8

    finalize_kernel<<<256, 256>>>(out, out_size);                    // 9
}